// round 15
// baseline (speedup 1.0000x reference)
#include <cuda_runtime.h>
#include <cstdint>

// snn_input: integrate-and-fire over T=32 steps, N=4194304 neurons.
//   per step: m += image[t]; spk = m >= 1.0f; m -= 1.0f if spk
// Output: [spikes (T*N, 0/1 float32), final mempot (N float32)].
//
// 1.056 GB irreducible traffic; plateau at ~6.6 TB/s across 8 configs
// (TBATCH 8/16/32, 128/256-bit, block 256/512), dram__cycles_active
// ~83-84% binding. R15 probe: drop .cs from STORES only (default
// write-back). .cs-evict-first drains dirty lines to DRAM in issue order,
// finely interleaving W with R at the controller; default policy lets the
// 126MB L2 batch writebacks into longer, bank-friendlier bursts -> fewer
// R/W turnarounds. Loads stay .cs (zero reuse, keep read data out of L2's
// dirty-line budget).

static constexpr int TSTEPS = 32;
static constexpr int TBATCH = 16;
static constexpr float THRES = 1.0f;

__global__ __launch_bounds__(512) void snn_if_kernel(
    const float4* __restrict__ image,    // [T, N/4] as float4
    const float4* __restrict__ mempot0,  // [N/4]
    float4* __restrict__ out,            // [T*N/4 spikes][N/4 mempot]
    int n4)
{
    int i = blockIdx.x * blockDim.x + threadIdx.x;   // grid covers n4 exactly

    float4 m = __ldcs(&mempot0[i]);

#pragma unroll
    for (int tb = 0; tb < TSTEPS / TBATCH; tb++) {
        float4 im[TBATCH];
        // front-batched loads: 16 independent LDG.E.128.CS in flight
#pragma unroll
        for (int j = 0; j < TBATCH; j++) {
            im[j] = __ldcs(&image[(size_t)(tb * TBATCH + j) * n4 + i]);
        }
        // compute + store burst (default write-back policy: let L2 batch
        // the DRAM writebacks instead of evict-first draining)
#pragma unroll
        for (int j = 0; j < TBATCH; j++) {
            m.x += im[j].x; m.y += im[j].y; m.z += im[j].z; m.w += im[j].w;
            float4 s;
            s.x = (m.x >= THRES) ? 1.0f : 0.0f;
            s.y = (m.y >= THRES) ? 1.0f : 0.0f;
            s.z = (m.z >= THRES) ? 1.0f : 0.0f;
            s.w = (m.w >= THRES) ? 1.0f : 0.0f;
            // thres == 1.0 so subtracting s == subtracting s*THRES
            m.x -= s.x; m.y -= s.y; m.z -= s.z; m.w -= s.w;
            out[(size_t)(tb * TBATCH + j) * n4 + i] = s;
        }
    }
    out[(size_t)TSTEPS * n4 + i] = m;
}

extern "C" void kernel_launch(void* const* d_in, const int* in_sizes, int n_in,
                              void* d_out, int out_size)
{
    const float4* image   = (const float4*)d_in[0];
    const float4* mempot0 = (const float4*)d_in[1];
    float4*       out     = (float4*)d_out;

    int n  = in_sizes[1];      // 4194304 neurons
    int n4 = n / 4;            // 1048576 float4 lanes (= 2048 * 512 exactly)

    const int threads = 512;
    const int blocks  = n4 / threads;
    snn_if_kernel<<<blocks, threads>>>(image, mempot0, out, n4);
}

// round 16
// speedup vs baseline: 1.0194x; 1.0194x over previous
#include <cuda_runtime.h>
#include <cstdint>

// snn_input: integrate-and-fire over T=32 steps, N=4194304 neurons.
//   per step: m += image[t]; spk = m >= 1.0f; m -= 1.0f if spk
// Output: [spikes (T*N, 0/1 float32), final mempot (N float32)].
//
// FINAL KERNEL. 1.056 GB irreducible traffic, byte-exact at DRAM
// (HBM GB/s x dur == mandated bytes). dram__cycles_active ~83% is the
// binding resource; L2 ~39%, all compute pipes idle (<7%).
//
// Fully bracketed search (9 configs, all post-mortemed):
//   TBATCH:   1/8/16/32  -> 16 best (32: regs 159, occ 11%, 174us)
//   width:    128b best; 256b v8.f32 neutral
//   layout:   lane-coalesced required (thread-consecutive pairs break
//             coalescing: L1 76%, DRAM 53%, 252us)
//   block:    256 (164.0) / 512 (163.6, best)
//   store:    .cs better than default write-back (163.6 vs 166.6)
//   occ:      flat 22%-89%; collapses only at 11%
// Plateau: 163.6-166.6us across all sane configs = the GB300 mixed
// 50/50 R/W streaming ceiling (~6.6 TB/s). Remaining gap to 8TB/s spec
// is DRAM-controller turnaround, unreachable from SASS (TMA shares the
// same path-independent memory-path ceiling).

static constexpr int TSTEPS = 32;
static constexpr int TBATCH = 16;
static constexpr float THRES = 1.0f;

__global__ __launch_bounds__(512) void snn_if_kernel(
    const float4* __restrict__ image,    // [T, N/4] as float4
    const float4* __restrict__ mempot0,  // [N/4]
    float4* __restrict__ out,            // [T*N/4 spikes][N/4 mempot]
    int n4)
{
    int i = blockIdx.x * blockDim.x + threadIdx.x;   // grid covers n4 exactly

    float4 m = __ldcs(&mempot0[i]);

#pragma unroll
    for (int tb = 0; tb < TSTEPS / TBATCH; tb++) {
        float4 im[TBATCH];
        // front-batched loads: 16 independent LDG.E.128.CS in flight
#pragma unroll
        for (int j = 0; j < TBATCH; j++) {
            im[j] = __ldcs(&image[(size_t)(tb * TBATCH + j) * n4 + i]);
        }
        // compute + store burst
#pragma unroll
        for (int j = 0; j < TBATCH; j++) {
            m.x += im[j].x; m.y += im[j].y; m.z += im[j].z; m.w += im[j].w;
            float4 s;
            s.x = (m.x >= THRES) ? 1.0f : 0.0f;
            s.y = (m.y >= THRES) ? 1.0f : 0.0f;
            s.z = (m.z >= THRES) ? 1.0f : 0.0f;
            s.w = (m.w >= THRES) ? 1.0f : 0.0f;
            // thres == 1.0 so subtracting s == subtracting s*THRES
            m.x -= s.x; m.y -= s.y; m.z -= s.z; m.w -= s.w;
            __stcs(&out[(size_t)(tb * TBATCH + j) * n4 + i], s);
        }
    }
    __stcs(&out[(size_t)TSTEPS * n4 + i], m);
}

extern "C" void kernel_launch(void* const* d_in, const int* in_sizes, int n_in,
                              void* d_out, int out_size)
{
    const float4* image   = (const float4*)d_in[0];
    const float4* mempot0 = (const float4*)d_in[1];
    float4*       out     = (float4*)d_out;

    int n  = in_sizes[1];      // 4194304 neurons
    int n4 = n / 4;            // 1048576 float4 lanes (= 2048 * 512 exactly)

    const int threads = 512;
    const int blocks  = n4 / threads;
    snn_if_kernel<<<blocks, threads>>>(image, mempot0, out, n4);
}

// round 17
// speedup vs baseline: 1.0266x; 1.0071x over previous
#include <cuda_runtime.h>
#include <cstdint>

// snn_input: integrate-and-fire over T=32 steps, N=4194304 neurons.
//   per step: m += image[t]; spk = m >= 1.0f; m -= 1.0f if spk
// Output: [spikes (T*N, 0/1 float32), final mempot (N float32)].
//
// 1.056 GB irreducible traffic; plateau 163.5-166.6us across 9 configs,
// dram__cycles_active ~83% binding, traffic byte-exact, compute idle.
// R17 (last structural probe): software-pipelined double buffer,
// TBATCH=8 — loads of batch k+1 issued BEFORE compute+store of batch k,
// so every warp keeps read AND write requests simultaneously in flight
// (no phase-boundary dip in controller read-queue occupancy).
// Same regs/occ as incumbent.

static constexpr int TSTEPS = 32;
static constexpr int TBATCH = 8;
static constexpr int NBATCH = TSTEPS / TBATCH;   // 4
static constexpr float THRES = 1.0f;

__device__ __forceinline__ void load_batch(float4* __restrict__ dst,
                                           const float4* __restrict__ image,
                                           int tb, int n4, int i)
{
#pragma unroll
    for (int j = 0; j < TBATCH; j++)
        dst[j] = __ldcs(&image[(size_t)(tb * TBATCH + j) * n4 + i]);
}

__device__ __forceinline__ void compute_store_batch(float4& m,
                                                    const float4* __restrict__ im,
                                                    float4* __restrict__ out,
                                                    int tb, int n4, int i)
{
#pragma unroll
    for (int j = 0; j < TBATCH; j++) {
        m.x += im[j].x; m.y += im[j].y; m.z += im[j].z; m.w += im[j].w;
        float4 s;
        s.x = (m.x >= THRES) ? 1.0f : 0.0f;
        s.y = (m.y >= THRES) ? 1.0f : 0.0f;
        s.z = (m.z >= THRES) ? 1.0f : 0.0f;
        s.w = (m.w >= THRES) ? 1.0f : 0.0f;
        // thres == 1.0 so subtracting s == subtracting s*THRES
        m.x -= s.x; m.y -= s.y; m.z -= s.z; m.w -= s.w;
        __stcs(&out[(size_t)(tb * TBATCH + j) * n4 + i], s);
    }
}

__global__ __launch_bounds__(512) void snn_if_kernel(
    const float4* __restrict__ image,    // [T, N/4] as float4
    const float4* __restrict__ mempot0,  // [N/4]
    float4* __restrict__ out,            // [T*N/4 spikes][N/4 mempot]
    int n4)
{
    int i = blockIdx.x * blockDim.x + threadIdx.x;   // grid covers n4 exactly

    float4 m = __ldcs(&mempot0[i]);

    float4 buf0[TBATCH], buf1[TBATCH];

    // prologue: fill buffer 0
    load_batch(buf0, image, 0, n4, i);

#pragma unroll
    for (int tb = 0; tb < NBATCH; tb++) {
        float4* cur  = (tb & 1) ? buf1 : buf0;
        float4* next = (tb & 1) ? buf0 : buf1;
        // issue next batch's loads BEFORE draining current batch:
        // keeps reads and writes concurrently in flight per warp
        if (tb + 1 < NBATCH)
            load_batch(next, image, tb + 1, n4, i);
        compute_store_batch(m, cur, out, tb, n4, i);
    }

    __stcs(&out[(size_t)TSTEPS * n4 + i], m);
}

extern "C" void kernel_launch(void* const* d_in, const int* in_sizes, int n_in,
                              void* d_out, int out_size)
{
    const float4* image   = (const float4*)d_in[0];
    const float4* mempot0 = (const float4*)d_in[1];
    float4*       out     = (float4*)d_out;

    int n  = in_sizes[1];      // 4194304 neurons
    int n4 = n / 4;            // 1048576 float4 lanes (= 2048 * 512 exactly)

    const int threads = 512;
    const int blocks  = n4 / threads;
    snn_if_kernel<<<blocks, threads>>>(image, mempot0, out, n4);
}